// round 9
// baseline (speedup 1.0000x reference)
#include <cuda_runtime.h>
#include <cuda_bf16.h>
#include <math.h>

#define BB 8
#define HH 256
#define LL 8192
#define NN 16
#define DTE 512
#define DI 512   // expand*H
#define O2 512   // 2*H

// ---------------- scratch (device globals; no allocation allowed) ----------
__device__ float  g_partt[BB*HH];
__device__ float2 g_stats[BB*LL];
__device__ float2 g_lam[HH*NN];
__device__ float2 g_c0[HH*NN];
__device__ float2 g_c1[HH*NN];
__device__ float  g_u [BB*HH*LL];   // u after LN1+part_t; later reused as yn (LN2 out)
__device__ float  g_yf[BB*HH*LL];   // fwd scan contrib; later y = gelu(yf+yb+u*D)
__device__ float  g_yb[BB*HH*LL];   // bwd scan contrib
__device__ float  g_z [BB*O2*LL];   // z (pre-GLU); later reused as h1 (FFN mid)
__device__ float  g_y1[BB*HH*LL];   // residual-1 output

// ---------------- helpers ---------------------------------------------------
__device__ __forceinline__ float gelu_t(float x) {
    float x3 = x * x * x;
    return 0.5f * x * (1.0f + tanhf(0.7978845608028654f * (x + 0.044715f * x3)));
}
__device__ __forceinline__ float sigm(float x) { return 1.0f / (1.0f + expf(-x)); }

// ---------------- setup: lambda and 2*C' coefficients -----------------------
__global__ void k_setup(const float* __restrict__ log_dt,
                        const float* __restrict__ A_re, const float* __restrict__ A_im,
                        const float* __restrict__ C_re, const float* __restrict__ C_im) {
    int h = blockIdx.x, n = threadIdx.x;
    int i = h * NN + n;
    float dt  = expf(log_dt[h]);
    float ar  = A_re[i] * dt, ai = A_im[i] * dt;    // dtA
    float e   = expf(ar);
    float lre = e * cosf(ai), lim = e * sinf(ai);   // lambda = exp(dtA)
    float Are = A_re[i], Aim = A_im[i];
    float den = Are * Are + Aim * Aim;
    float num_r = lre - 1.0f, num_i = lim;
    float fre = (num_r * Are + num_i * Aim) / den;  // (lambda-1)/A
    float fim = (num_i * Are - num_r * Aim) / den;
    float c0r = C_re[i], c0i = C_im[i];
    float c1r = C_re[HH*NN + i], c1i = C_im[HH*NN + i];
    g_lam[i] = make_float2(lre, lim);
    g_c0[i]  = make_float2(2.0f*(c0r*fre - c0i*fim), 2.0f*(c0r*fim + c0i*fre));
    g_c1[i]  = make_float2(2.0f*(c1r*fre - c1i*fim), 2.0f*(c1r*fim + c1i*fre));
}

// ---------------- part_t = emb @ fc_t_w^T + b -------------------------------
__global__ void k_partt(const float* __restrict__ emb, const float* __restrict__ w,
                        const float* __restrict__ bias) {
    int gw   = blockIdx.x * 8 + (threadIdx.x >> 5);  // warp id: one per (b,h)
    int lane = threadIdx.x & 31;
    int b = gw >> 8, h = gw & 255;
    float s = 0.f;
    #pragma unroll
    for (int k = lane; k < DTE; k += 32)
        s += emb[b*DTE + k] * w[h*DTE + k];
    #pragma unroll
    for (int o = 16; o > 0; o >>= 1) s += __shfl_xor_sync(0xffffffffu, s, o);
    if (lane == 0) g_partt[b*HH + h] = s + bias[h];
}

// ---------------- per-(b,l) mean/rstd over H --------------------------------
__global__ void k_stats(const float* __restrict__ inp) {
    int b = blockIdx.y;
    int l = blockIdx.x * 256 + threadIdx.x;
    const float* p = inp + (size_t)b * HH * LL + l;
    float s = 0.f, sq = 0.f;
    #pragma unroll 8
    for (int h = 0; h < HH; h++) {
        float v = p[(size_t)h * LL];
        s += v; sq += v * v;
    }
    float mean = s * (1.0f / HH);
    float var  = sq * (1.0f / HH) - mean * mean;
    float rstd = rsqrtf(fmaxf(var, 1e-20f));
    g_stats[b*LL + l] = make_float2(mean, rstd);
}

// ---------------- LN1 + part_t -> u -----------------------------------------
__global__ void k_norm1(const float* __restrict__ x,
                        const float* __restrict__ n_m, const float* __restrict__ n_s) {
    float m0 = *n_m, s0 = *n_s;
    size_t i4 = (size_t)blockIdx.x * 256 + threadIdx.x;
    size_t idx = i4 * 4;
    int l = (int)(idx & (LL - 1));
    int h = (int)((idx >> 13) & (HH - 1));
    int b = (int)(idx >> 21);
    float pt = g_partt[b*HH + h];
    float4 xv = *(const float4*)(x + idx);
    float4 o;
    float2 st;
    st = g_stats[b*LL + l + 0]; o.x = s0*st.y*(xv.x - st.x + m0) + pt;
    st = g_stats[b*LL + l + 1]; o.y = s0*st.y*(xv.y - st.x + m0) + pt;
    st = g_stats[b*LL + l + 2]; o.z = s0*st.y*(xv.z - st.x + m0) + pt;
    st = g_stats[b*LL + l + 3]; o.w = s0*st.y*(xv.w - st.x + m0) + pt;
    *(float4*)(g_u + idx) = o;
}

// ---------------- bidirectional diagonal SSM scan ---------------------------
// warp = 2 heads x 16 modes/lane; gridDim.y selects direction.
__global__ void k_scan() {
    int warp = threadIdx.x >> 5, lane = threadIdx.x & 31;
    int pair = blockIdx.x * 4 + warp;          // 0..1023
    int sub  = lane >> 4, n = lane & 15;
    int bh   = pair * 2 + sub;                 // 0..2047
    int h    = bh & 255;
    int dir  = blockIdx.y;
    float2 lam = g_lam[h*NN + n];
    float2 c   = (dir == 0 ? g_c0 : g_c1)[h*NN + n];
    const float* u = g_u + (size_t)bh * LL;
    float* out = (dir == 0 ? g_yf : g_yb) + (size_t)bh * LL;
    float sr = 0.f, si = 0.f;
    if (dir == 0) {
        for (int l = 0; l < LL; l += 4) {
            float4 uv = *(const float4*)(u + l);
            float y0, y1, y2, y3, nr;
            nr = fmaf(lam.x, sr, fmaf(-lam.y, si, uv.x)); si = fmaf(lam.x, si, lam.y*sr); sr = nr;
            y0 = c.x*sr - c.y*si;
            nr = fmaf(lam.x, sr, fmaf(-lam.y, si, uv.y)); si = fmaf(lam.x, si, lam.y*sr); sr = nr;
            y1 = c.x*sr - c.y*si;
            nr = fmaf(lam.x, sr, fmaf(-lam.y, si, uv.z)); si = fmaf(lam.x, si, lam.y*sr); sr = nr;
            y2 = c.x*sr - c.y*si;
            nr = fmaf(lam.x, sr, fmaf(-lam.y, si, uv.w)); si = fmaf(lam.x, si, lam.y*sr); sr = nr;
            y3 = c.x*sr - c.y*si;
            #pragma unroll
            for (int o = 8; o > 0; o >>= 1) {
                y0 += __shfl_xor_sync(0xffffffffu, y0, o);
                y1 += __shfl_xor_sync(0xffffffffu, y1, o);
                y2 += __shfl_xor_sync(0xffffffffu, y2, o);
                y3 += __shfl_xor_sync(0xffffffffu, y3, o);
            }
            if (n == 0) *(float4*)(out + l) = make_float4(y0, y1, y2, y3);
        }
    } else {
        // t[l] = u[l+1] + lam*t[l+1]; y[l] = 2Re(c1' t[l])
        for (int l = LL - 1; l >= 3; l -= 4) {
            float4 uv = *(const float4*)(u + l - 3);   // u[l-3..l]
            float y0, y1, y2, y3, nr;
            y0 = c.x*sr - c.y*si;   // at l
            nr = fmaf(lam.x, sr, fmaf(-lam.y, si, uv.w)); si = fmaf(lam.x, si, lam.y*sr); sr = nr;
            y1 = c.x*sr - c.y*si;   // at l-1
            nr = fmaf(lam.x, sr, fmaf(-lam.y, si, uv.z)); si = fmaf(lam.x, si, lam.y*sr); sr = nr;
            y2 = c.x*sr - c.y*si;   // at l-2
            nr = fmaf(lam.x, sr, fmaf(-lam.y, si, uv.y)); si = fmaf(lam.x, si, lam.y*sr); sr = nr;
            y3 = c.x*sr - c.y*si;   // at l-3
            nr = fmaf(lam.x, sr, fmaf(-lam.y, si, uv.x)); si = fmaf(lam.x, si, lam.y*sr); sr = nr;
            #pragma unroll
            for (int o = 8; o > 0; o >>= 1) {
                y0 += __shfl_xor_sync(0xffffffffu, y0, o);
                y1 += __shfl_xor_sync(0xffffffffu, y1, o);
                y2 += __shfl_xor_sync(0xffffffffu, y2, o);
                y3 += __shfl_xor_sync(0xffffffffu, y3, o);
            }
            if (n == 0) *(float4*)(out + l - 3) = make_float4(y3, y2, y1, y0);
        }
    }
}

// ---------------- combine: y = gelu(yf + yb + u*D) -> g_yf ------------------
__global__ void k_combine(const float* __restrict__ D) {
    size_t i4 = (size_t)blockIdx.x * 256 + threadIdx.x;
    size_t idx = i4 * 4;
    int h = (int)((idx >> 13) & (HH - 1));
    float d = D[h];
    float4 a = *(const float4*)(g_yf + idx);
    float4 bv = *(const float4*)(g_yb + idx);
    float4 uv = *(const float4*)(g_u + idx);
    float4 o;
    o.x = gelu_t(a.x + bv.x + uv.x * d);
    o.y = gelu_t(a.y + bv.y + uv.y * d);
    o.z = gelu_t(a.z + bv.z + uv.z * d);
    o.w = gelu_t(a.w + bv.w + uv.w * d);
    *(float4*)(g_yf + idx) = o;
}

// ---------------- GLU + residual: y1 = x + z1*sigmoid(z2) -------------------
__global__ void k_glu(const float* __restrict__ x, const float* __restrict__ out_b) {
    size_t i4 = (size_t)blockIdx.x * 256 + threadIdx.x;
    size_t idx = i4 * 4;
    int l = (int)(idx & (LL - 1));
    int h = (int)((idx >> 13) & (HH - 1));
    int b = (int)(idx >> 21);
    float b1 = out_b[h], b2 = out_b[h + HH];
    const float* z1 = g_z + ((size_t)b * O2 + h) * LL + l;
    const float* z2 = g_z + ((size_t)b * O2 + h + HH) * LL + l;
    float4 a = *(const float4*)z1;
    float4 g = *(const float4*)z2;
    float4 xv = *(const float4*)(x + idx);
    float4 o;
    o.x = xv.x + (a.x + b1) * sigm(g.x + b2);
    o.y = xv.y + (a.y + b1) * sigm(g.y + b2);
    o.z = xv.z + (a.z + b1) * sigm(g.z + b2);
    o.w = xv.w + (a.w + b1) * sigm(g.w + b2);
    *(float4*)(g_y1 + idx) = o;
}

// ---------------- LN2 -> yn (into g_u) --------------------------------------
__global__ void k_norm2(const float* __restrict__ n_m, const float* __restrict__ n_s) {
    float m0 = *n_m, s0 = *n_s;
    size_t i4 = (size_t)blockIdx.x * 256 + threadIdx.x;
    size_t idx = i4 * 4;
    int l = (int)(idx & (LL - 1));
    int b = (int)(idx >> 21);
    float4 xv = *(const float4*)(g_y1 + idx);
    float4 o;
    float2 st;
    st = g_stats[b*LL + l + 0]; o.x = s0*st.y*(xv.x - st.x + m0);
    st = g_stats[b*LL + l + 1]; o.y = s0*st.y*(xv.y - st.x + m0);
    st = g_stats[b*LL + l + 2]; o.z = s0*st.y*(xv.z - st.x + m0);
    st = g_stats[b*LL + l + 3]; o.w = s0*st.y*(xv.w - st.x + m0);
    *(float4*)(g_u + idx) = o;
}

// ---------------- SGEMM: C[b,m,l] = sum_k A[m,k] * Bm[b,k,l] ----------------
// EPI 0: plain.  EPI 1: gelu(v+bias[m]).  EPI 2: v+bias[m]+res[b,m,l].
#define BM 128
#define BN 128
#define BK 8
template <int EPI>
__global__ void __launch_bounds__(256, 2)
gemm_kernel(const float* __restrict__ A, const float* __restrict__ Bm,
            float* __restrict__ C, const float* __restrict__ bias,
            const float* __restrict__ res, int M, int K) {
    __shared__ float As[BK][BM];
    __shared__ float Bs[BK][BN];
    int b = blockIdx.z;
    const float* Bp = Bm + (size_t)b * K * LL;
    float*       Cp = C  + (size_t)b * M * LL;
    const float* Rp = (EPI == 2) ? (res + (size_t)b * M * LL) : nullptr;

    int tid = threadIdx.x;
    int m0 = blockIdx.y * BM, n0 = blockIdx.x * BN;
    int a_row = tid >> 1,  a_col = (tid & 1) * 4;
    int b_row = tid >> 5,  b_col = (tid & 31) * 4;
    int ty = tid >> 4, tx = tid & 15;

    float acc[8][8];
    #pragma unroll
    for (int i = 0; i < 8; i++)
        #pragma unroll
        for (int j = 0; j < 8; j++) acc[i][j] = 0.f;

    for (int k0 = 0; k0 < K; k0 += BK) {
        float4 av = *(const float4*)(A + (size_t)(m0 + a_row) * K + k0 + a_col);
        As[a_col + 0][a_row] = av.x;
        As[a_col + 1][a_row] = av.y;
        As[a_col + 2][a_row] = av.z;
        As[a_col + 3][a_row] = av.w;
        *(float4*)&Bs[b_row][b_col] =
            *(const float4*)(Bp + (size_t)(k0 + b_row) * LL + n0 + b_col);
        __syncthreads();
        #pragma unroll
        for (int k = 0; k < BK; k++) {
            float ar[8], br[8];
            *(float4*)&ar[0] = *(const float4*)&As[k][ty * 8];
            *(float4*)&ar[4] = *(const float4*)&As[k][ty * 8 + 4];
            *(float4*)&br[0] = *(const float4*)&Bs[k][tx * 8];
            *(float4*)&br[4] = *(const float4*)&Bs[k][tx * 8 + 4];
            #pragma unroll
            for (int i = 0; i < 8; i++)
                #pragma unroll
                for (int j = 0; j < 8; j++)
                    acc[i][j] = fmaf(ar[i], br[j], acc[i][j]);
        }
        __syncthreads();
    }

    #pragma unroll
    for (int i = 0; i < 8; i++) {
        int m = m0 + ty * 8 + i;
        size_t rowoff = (size_t)m * LL + n0 + tx * 8;
        float bs = (EPI != 0) ? bias[m] : 0.f;
        float v[8];
        #pragma unroll
        for (int j = 0; j < 8; j++) {
            float t = acc[i][j];
            if (EPI == 1) t = gelu_t(t + bs);
            if (EPI == 2) t = t + bs + Rp[rowoff + j];
            v[j] = t;
        }
        *(float4*)(Cp + rowoff)     = make_float4(v[0], v[1], v[2], v[3]);
        *(float4*)(Cp + rowoff + 4) = make_float4(v[4], v[5], v[6], v[7]);
    }
}

// ---------------- launch ----------------------------------------------------
extern "C" void kernel_launch(void* const* d_in, const int* in_sizes, int n_in,
                              void* d_out, int out_size) {
    const float* x      = (const float*)d_in[0];
    const float* emb    = (const float*)d_in[1];
    const float* fc_t_w = (const float*)d_in[2];
    const float* fc_t_b = (const float*)d_in[3];
    const float* log_dt = (const float*)d_in[4];
    const float* A_re   = (const float*)d_in[5];
    const float* A_im   = (const float*)d_in[6];
    const float* C_re   = (const float*)d_in[7];
    const float* C_im   = (const float*)d_in[8];
    const float* Dp     = (const float*)d_in[9];
    const float* out_w  = (const float*)d_in[10];
    const float* out_b  = (const float*)d_in[11];
    const float* n1_m   = (const float*)d_in[12];
    const float* n1_s   = (const float*)d_in[13];
    const float* n2_m   = (const float*)d_in[14];
    const float* n2_s   = (const float*)d_in[15];
    const float* ff_w1  = (const float*)d_in[16];
    const float* ff_b1  = (const float*)d_in[17];
    const float* ff_w2  = (const float*)d_in[18];
    const float* ff_b2  = (const float*)d_in[19];
    float* out = (float*)d_out;

    float *p_yf, *p_z, *p_u, *p_y1;
    cudaGetSymbolAddress((void**)&p_yf, g_yf);
    cudaGetSymbolAddress((void**)&p_z,  g_z);
    cudaGetSymbolAddress((void**)&p_u,  g_u);
    cudaGetSymbolAddress((void**)&p_y1, g_y1);

    const int EW_BLOCKS = (BB * HH * LL) / (256 * 4);  // 16384

    k_setup<<<HH, NN>>>(log_dt, A_re, A_im, C_re, C_im);
    k_partt<<<(BB * HH) / 8, 256>>>(emb, fc_t_w, fc_t_b);
    k_stats<<<dim3(LL / 256, BB), 256>>>(x);
    k_norm1<<<EW_BLOCKS, 256>>>(x, n1_m, n1_s);
    k_scan<<<dim3((BB * HH) / 8, 2), 128>>>();
    k_combine<<<EW_BLOCKS, 256>>>(Dp);
    // z = out_w @ y
    gemm_kernel<0><<<dim3(LL / BN, O2 / BM, BB), 256>>>(out_w, p_yf, p_z,
                                                        nullptr, nullptr, O2, HH);
    k_glu<<<EW_BLOCKS, 256>>>(x, out_b);
    k_stats<<<dim3(LL / 256, BB), 256>>>(p_y1);
    k_norm2<<<EW_BLOCKS, 256>>>(n2_m, n2_s);
    // h1 = gelu(ff_w1 @ yn + b1)  (yn in g_u, h1 overwrites g_z)
    gemm_kernel<1><<<dim3(LL / BN, DI / BM, BB), 256>>>(ff_w1, p_u, p_z,
                                                        ff_b1, nullptr, DI, HH);
    // out = y1 + ff_w2 @ h1 + b2
    gemm_kernel<2><<<dim3(LL / BN, HH / BM, BB), 256>>>(ff_w2, p_z, out,
                                                        ff_b2, p_y1, HH, DI);
}

// round 10
// speedup vs baseline: 1.0008x; 1.0008x over previous
#include <cuda_runtime.h>
#include <cuda_bf16.h>
#include <math.h>

#define BB 8
#define HH 256
#define LL 8192
#define NN 16
#define DTE 512
#define DI 512   // expand*H
#define O2 512   // 2*H

// ---------------- scratch (device globals; no allocation allowed) ----------
__device__ float  g_partt[BB*HH];
__device__ float2 g_stats[BB*LL];
__device__ float2 g_lam[HH*NN];
__device__ float2 g_c0[HH*NN];
__device__ float2 g_c1[HH*NN];
__device__ float  g_u [BB*HH*LL];   // u after LN1+part_t; later reused as yn (LN2 out)
__device__ float  g_yf[BB*HH*LL];   // fwd scan contrib; later y = gelu(yf+yb+u*D)
__device__ float  g_yb[BB*HH*LL];   // bwd scan contrib
__device__ float  g_z [BB*O2*LL];   // z (pre-GLU); later reused as h1 (FFN mid)
__device__ float  g_y1[BB*HH*LL];   // residual-1 output

// ---------------- helpers ---------------------------------------------------
__device__ __forceinline__ float gelu_t(float x) {
    float x3 = x * x * x;
    return 0.5f * x * (1.0f + tanhf(0.7978845608028654f * (x + 0.044715f * x3)));
}
__device__ __forceinline__ float sigm(float x) { return 1.0f / (1.0f + expf(-x)); }

// ---------------- setup: lambda and 2*C' coefficients -----------------------
__global__ void k_setup(const float* __restrict__ log_dt,
                        const float* __restrict__ A_re, const float* __restrict__ A_im,
                        const float* __restrict__ C_re, const float* __restrict__ C_im) {
    int h = blockIdx.x, n = threadIdx.x;
    int i = h * NN + n;
    float dt  = expf(log_dt[h]);
    float ar  = A_re[i] * dt, ai = A_im[i] * dt;    // dtA
    float e   = expf(ar);
    float lre = e * cosf(ai), lim = e * sinf(ai);   // lambda = exp(dtA)
    float Are = A_re[i], Aim = A_im[i];
    float den = Are * Are + Aim * Aim;
    float num_r = lre - 1.0f, num_i = lim;
    float fre = (num_r * Are + num_i * Aim) / den;  // (lambda-1)/A
    float fim = (num_i * Are - num_r * Aim) / den;
    float c0r = C_re[i], c0i = C_im[i];
    float c1r = C_re[HH*NN + i], c1i = C_im[HH*NN + i];
    g_lam[i] = make_float2(lre, lim);
    g_c0[i]  = make_float2(2.0f*(c0r*fre - c0i*fim), 2.0f*(c0r*fim + c0i*fre));
    g_c1[i]  = make_float2(2.0f*(c1r*fre - c1i*fim), 2.0f*(c1r*fim + c1i*fre));
}

// ---------------- part_t = emb @ fc_t_w^T + b -------------------------------
__global__ void k_partt(const float* __restrict__ emb, const float* __restrict__ w,
                        const float* __restrict__ bias) {
    int gw   = blockIdx.x * 8 + (threadIdx.x >> 5);  // warp id: one per (b,h)
    int lane = threadIdx.x & 31;
    int b = gw >> 8, h = gw & 255;
    float s = 0.f;
    #pragma unroll
    for (int k = lane; k < DTE; k += 32)
        s += emb[b*DTE + k] * w[h*DTE + k];
    #pragma unroll
    for (int o = 16; o > 0; o >>= 1) s += __shfl_xor_sync(0xffffffffu, s, o);
    if (lane == 0) g_partt[b*HH + h] = s + bias[h];
}

// ---------------- per-(b,l) mean/rstd over H --------------------------------
__global__ void k_stats(const float* __restrict__ inp) {
    int b = blockIdx.y;
    int l = blockIdx.x * 256 + threadIdx.x;
    const float* p = inp + (size_t)b * HH * LL + l;
    float s = 0.f, sq = 0.f;
    #pragma unroll 8
    for (int h = 0; h < HH; h++) {
        float v = p[(size_t)h * LL];
        s += v; sq += v * v;
    }
    float mean = s * (1.0f / HH);
    float var  = sq * (1.0f / HH) - mean * mean;
    float rstd = rsqrtf(fmaxf(var, 1e-20f));
    g_stats[b*LL + l] = make_float2(mean, rstd);
}

// ---------------- LN1 + part_t -> u -----------------------------------------
__global__ void k_norm1(const float* __restrict__ x,
                        const float* __restrict__ n_m, const float* __restrict__ n_s) {
    float m0 = *n_m, s0 = *n_s;
    size_t i4 = (size_t)blockIdx.x * 256 + threadIdx.x;
    size_t idx = i4 * 4;
    int l = (int)(idx & (LL - 1));
    int h = (int)((idx >> 13) & (HH - 1));
    int b = (int)(idx >> 21);
    float pt = g_partt[b*HH + h];
    float4 xv = *(const float4*)(x + idx);
    float4 o;
    float2 st;
    st = g_stats[b*LL + l + 0]; o.x = s0*st.y*(xv.x - st.x + m0) + pt;
    st = g_stats[b*LL + l + 1]; o.y = s0*st.y*(xv.y - st.x + m0) + pt;
    st = g_stats[b*LL + l + 2]; o.z = s0*st.y*(xv.z - st.x + m0) + pt;
    st = g_stats[b*LL + l + 3]; o.w = s0*st.y*(xv.w - st.x + m0) + pt;
    *(float4*)(g_u + idx) = o;
}

// ---------------- bidirectional diagonal SSM scan ---------------------------
// warp = 2 heads x 16 modes/lane; gridDim.y selects direction.
__global__ void k_scan() {
    int warp = threadIdx.x >> 5, lane = threadIdx.x & 31;
    int pair = blockIdx.x * 4 + warp;          // 0..1023
    int sub  = lane >> 4, n = lane & 15;
    int bh   = pair * 2 + sub;                 // 0..2047
    int h    = bh & 255;
    int dir  = blockIdx.y;
    float2 lam = g_lam[h*NN + n];
    float2 c   = (dir == 0 ? g_c0 : g_c1)[h*NN + n];
    const float* u = g_u + (size_t)bh * LL;
    float* out = (dir == 0 ? g_yf : g_yb) + (size_t)bh * LL;
    float sr = 0.f, si = 0.f;
    if (dir == 0) {
        for (int l = 0; l < LL; l += 4) {
            float4 uv = *(const float4*)(u + l);
            float y0, y1, y2, y3, nr;
            nr = fmaf(lam.x, sr, fmaf(-lam.y, si, uv.x)); si = fmaf(lam.x, si, lam.y*sr); sr = nr;
            y0 = c.x*sr - c.y*si;
            nr = fmaf(lam.x, sr, fmaf(-lam.y, si, uv.y)); si = fmaf(lam.x, si, lam.y*sr); sr = nr;
            y1 = c.x*sr - c.y*si;
            nr = fmaf(lam.x, sr, fmaf(-lam.y, si, uv.z)); si = fmaf(lam.x, si, lam.y*sr); sr = nr;
            y2 = c.x*sr - c.y*si;
            nr = fmaf(lam.x, sr, fmaf(-lam.y, si, uv.w)); si = fmaf(lam.x, si, lam.y*sr); sr = nr;
            y3 = c.x*sr - c.y*si;
            #pragma unroll
            for (int o = 8; o > 0; o >>= 1) {
                y0 += __shfl_xor_sync(0xffffffffu, y0, o);
                y1 += __shfl_xor_sync(0xffffffffu, y1, o);
                y2 += __shfl_xor_sync(0xffffffffu, y2, o);
                y3 += __shfl_xor_sync(0xffffffffu, y3, o);
            }
            if (n == 0) *(float4*)(out + l) = make_float4(y0, y1, y2, y3);
        }
    } else {
        // t[l] = u[l+1] + lam*t[l+1]; y[l] = 2Re(c1' t[l])
        for (int l = LL - 1; l >= 3; l -= 4) {
            float4 uv = *(const float4*)(u + l - 3);   // u[l-3..l]
            float y0, y1, y2, y3, nr;
            y0 = c.x*sr - c.y*si;   // at l
            nr = fmaf(lam.x, sr, fmaf(-lam.y, si, uv.w)); si = fmaf(lam.x, si, lam.y*sr); sr = nr;
            y1 = c.x*sr - c.y*si;   // at l-1
            nr = fmaf(lam.x, sr, fmaf(-lam.y, si, uv.z)); si = fmaf(lam.x, si, lam.y*sr); sr = nr;
            y2 = c.x*sr - c.y*si;   // at l-2
            nr = fmaf(lam.x, sr, fmaf(-lam.y, si, uv.y)); si = fmaf(lam.x, si, lam.y*sr); sr = nr;
            y3 = c.x*sr - c.y*si;   // at l-3
            nr = fmaf(lam.x, sr, fmaf(-lam.y, si, uv.x)); si = fmaf(lam.x, si, lam.y*sr); sr = nr;
            #pragma unroll
            for (int o = 8; o > 0; o >>= 1) {
                y0 += __shfl_xor_sync(0xffffffffu, y0, o);
                y1 += __shfl_xor_sync(0xffffffffu, y1, o);
                y2 += __shfl_xor_sync(0xffffffffu, y2, o);
                y3 += __shfl_xor_sync(0xffffffffu, y3, o);
            }
            if (n == 0) *(float4*)(out + l - 3) = make_float4(y3, y2, y1, y0);
        }
    }
}

// ---------------- combine: y = gelu(yf + yb + u*D) -> g_yf ------------------
__global__ void k_combine(const float* __restrict__ D) {
    size_t i4 = (size_t)blockIdx.x * 256 + threadIdx.x;
    size_t idx = i4 * 4;
    int h = (int)((idx >> 13) & (HH - 1));
    float d = D[h];
    float4 a = *(const float4*)(g_yf + idx);
    float4 bv = *(const float4*)(g_yb + idx);
    float4 uv = *(const float4*)(g_u + idx);
    float4 o;
    o.x = gelu_t(a.x + bv.x + uv.x * d);
    o.y = gelu_t(a.y + bv.y + uv.y * d);
    o.z = gelu_t(a.z + bv.z + uv.z * d);
    o.w = gelu_t(a.w + bv.w + uv.w * d);
    *(float4*)(g_yf + idx) = o;
}

// ---------------- GLU + residual: y1 = x + z1*sigmoid(z2) -------------------
__global__ void k_glu(const float* __restrict__ x, const float* __restrict__ out_b) {
    size_t i4 = (size_t)blockIdx.x * 256 + threadIdx.x;
    size_t idx = i4 * 4;
    int l = (int)(idx & (LL - 1));
    int h = (int)((idx >> 13) & (HH - 1));
    int b = (int)(idx >> 21);
    float b1 = out_b[h], b2 = out_b[h + HH];
    const float* z1 = g_z + ((size_t)b * O2 + h) * LL + l;
    const float* z2 = g_z + ((size_t)b * O2 + h + HH) * LL + l;
    float4 a = *(const float4*)z1;
    float4 g = *(const float4*)z2;
    float4 xv = *(const float4*)(x + idx);
    float4 o;
    o.x = xv.x + (a.x + b1) * sigm(g.x + b2);
    o.y = xv.y + (a.y + b1) * sigm(g.y + b2);
    o.z = xv.z + (a.z + b1) * sigm(g.z + b2);
    o.w = xv.w + (a.w + b1) * sigm(g.w + b2);
    *(float4*)(g_y1 + idx) = o;
}

// ---------------- LN2 -> yn (into g_u) --------------------------------------
__global__ void k_norm2(const float* __restrict__ n_m, const float* __restrict__ n_s) {
    float m0 = *n_m, s0 = *n_s;
    size_t i4 = (size_t)blockIdx.x * 256 + threadIdx.x;
    size_t idx = i4 * 4;
    int l = (int)(idx & (LL - 1));
    int b = (int)(idx >> 21);
    float4 xv = *(const float4*)(g_y1 + idx);
    float4 o;
    float2 st;
    st = g_stats[b*LL + l + 0]; o.x = s0*st.y*(xv.x - st.x + m0);
    st = g_stats[b*LL + l + 1]; o.y = s0*st.y*(xv.y - st.x + m0);
    st = g_stats[b*LL + l + 2]; o.z = s0*st.y*(xv.z - st.x + m0);
    st = g_stats[b*LL + l + 3]; o.w = s0*st.y*(xv.w - st.x + m0);
    *(float4*)(g_u + idx) = o;
}

// ---------------- SGEMM: C[b,m,l] = sum_k A[m,k] * Bm[b,k,l] ----------------
// EPI 0: plain.  EPI 1: gelu(v+bias[m]).  EPI 2: v+bias[m]+res[b,m,l].
#define BM 128
#define BN 128
#define BK 8
template <int EPI>
__global__ void __launch_bounds__(256, 2)
gemm_kernel(const float* __restrict__ A, const float* __restrict__ Bm,
            float* __restrict__ C, const float* __restrict__ bias,
            const float* __restrict__ res, int M, int K) {
    __shared__ float As[BK][BM];
    __shared__ float Bs[BK][BN];
    int b = blockIdx.z;
    const float* Bp = Bm + (size_t)b * K * LL;
    float*       Cp = C  + (size_t)b * M * LL;
    const float* Rp = (EPI == 2) ? (res + (size_t)b * M * LL) : nullptr;

    int tid = threadIdx.x;
    int m0 = blockIdx.y * BM, n0 = blockIdx.x * BN;
    int a_row = tid >> 1,  a_col = (tid & 1) * 4;
    int b_row = tid >> 5,  b_col = (tid & 31) * 4;
    int ty = tid >> 4, tx = tid & 15;

    float acc[8][8];
    #pragma unroll
    for (int i = 0; i < 8; i++)
        #pragma unroll
        for (int j = 0; j < 8; j++) acc[i][j] = 0.f;

    for (int k0 = 0; k0 < K; k0 += BK) {
        float4 av = *(const float4*)(A + (size_t)(m0 + a_row) * K + k0 + a_col);
        As[a_col + 0][a_row] = av.x;
        As[a_col + 1][a_row] = av.y;
        As[a_col + 2][a_row] = av.z;
        As[a_col + 3][a_row] = av.w;
        *(float4*)&Bs[b_row][b_col] =
            *(const float4*)(Bp + (size_t)(k0 + b_row) * LL + n0 + b_col);
        __syncthreads();
        #pragma unroll
        for (int k = 0; k < BK; k++) {
            float ar[8], br[8];
            *(float4*)&ar[0] = *(const float4*)&As[k][ty * 8];
            *(float4*)&ar[4] = *(const float4*)&As[k][ty * 8 + 4];
            *(float4*)&br[0] = *(const float4*)&Bs[k][tx * 8];
            *(float4*)&br[4] = *(const float4*)&Bs[k][tx * 8 + 4];
            #pragma unroll
            for (int i = 0; i < 8; i++)
                #pragma unroll
                for (int j = 0; j < 8; j++)
                    acc[i][j] = fmaf(ar[i], br[j], acc[i][j]);
        }
        __syncthreads();
    }

    #pragma unroll
    for (int i = 0; i < 8; i++) {
        int m = m0 + ty * 8 + i;
        size_t rowoff = (size_t)m * LL + n0 + tx * 8;
        float bs = (EPI != 0) ? bias[m] : 0.f;
        float v[8];
        #pragma unroll
        for (int j = 0; j < 8; j++) {
            float t = acc[i][j];
            if (EPI == 1) t = gelu_t(t + bs);
            if (EPI == 2) t = t + bs + Rp[rowoff + j];
            v[j] = t;
        }
        *(float4*)(Cp + rowoff)     = make_float4(v[0], v[1], v[2], v[3]);
        *(float4*)(Cp + rowoff + 4) = make_float4(v[4], v[5], v[6], v[7]);
    }
}

// ---------------- launch ----------------------------------------------------
extern "C" void kernel_launch(void* const* d_in, const int* in_sizes, int n_in,
                              void* d_out, int out_size) {
    const float* x      = (const float*)d_in[0];
    const float* emb    = (const float*)d_in[1];
    const float* fc_t_w = (const float*)d_in[2];
    const float* fc_t_b = (const float*)d_in[3];
    const float* log_dt = (const float*)d_in[4];
    const float* A_re   = (const float*)d_in[5];
    const float* A_im   = (const float*)d_in[6];
    const float* C_re   = (const float*)d_in[7];
    const float* C_im   = (const float*)d_in[8];
    const float* Dp     = (const float*)d_in[9];
    const float* out_w  = (const float*)d_in[10];
    const float* out_b  = (const float*)d_in[11];
    const float* n1_m   = (const float*)d_in[12];
    const float* n1_s   = (const float*)d_in[13];
    const float* n2_m   = (const float*)d_in[14];
    const float* n2_s   = (const float*)d_in[15];
    const float* ff_w1  = (const float*)d_in[16];
    const float* ff_b1  = (const float*)d_in[17];
    const float* ff_w2  = (const float*)d_in[18];
    const float* ff_b2  = (const float*)d_in[19];
    float* out = (float*)d_out;

    float *p_yf, *p_z, *p_u, *p_y1;
    cudaGetSymbolAddress((void**)&p_yf, g_yf);
    cudaGetSymbolAddress((void**)&p_z,  g_z);
    cudaGetSymbolAddress((void**)&p_u,  g_u);
    cudaGetSymbolAddress((void**)&p_y1, g_y1);

    const int EW_BLOCKS = (BB * HH * LL) / (256 * 4);  // 16384

    k_setup<<<HH, NN>>>(log_dt, A_re, A_im, C_re, C_im);
    k_partt<<<(BB * HH) / 8, 256>>>(emb, fc_t_w, fc_t_b);
    k_stats<<<dim3(LL / 256, BB), 256>>>(x);
    k_norm1<<<EW_BLOCKS, 256>>>(x, n1_m, n1_s);
    k_scan<<<dim3((BB * HH) / 8, 2), 128>>>();
    k_combine<<<EW_BLOCKS, 256>>>(Dp);
    // z = out_w @ y
    gemm_kernel<0><<<dim3(LL / BN, O2 / BM, BB), 256>>>(out_w, p_yf, p_z,
                                                        nullptr, nullptr, O2, HH);
    k_glu<<<EW_BLOCKS, 256>>>(x, out_b);
    k_stats<<<dim3(LL / 256, BB), 256>>>(p_y1);
    k_norm2<<<EW_BLOCKS, 256>>>(n2_m, n2_s);
    // h1 = gelu(ff_w1 @ yn + b1)  (yn in g_u, h1 overwrites g_z)
    gemm_kernel<1><<<dim3(LL / BN, DI / BM, BB), 256>>>(ff_w1, p_u, p_z,
                                                        ff_b1, nullptr, DI, HH);
    // out = y1 + ff_w2 @ h1 + b2
    gemm_kernel<2><<<dim3(LL / BN, HH / BM, BB), 256>>>(ff_w2, p_z, out,
                                                        ff_b2, p_y1, HH, DI);
}

// round 11
// speedup vs baseline: 1.5147x; 1.5135x over previous
#include <cuda_runtime.h>
#include <cuda_bf16.h>
#include <math.h>
#include <stdint.h>

#define BB 8
#define HH 256
#define LL 8192
#define NN 16
#define DTE 512
#define DI 512   // expand*H
#define O2 512   // 2*H

// ---------------- scratch (device globals; no allocation allowed) ----------
__device__ float  g_partt[BB*HH];
__device__ float2 g_stats[BB*LL];
__device__ float2 g_lam[HH*NN];
__device__ float2 g_c0[HH*NN];
__device__ float2 g_c1[HH*NN];
__device__ float  g_u [BB*HH*LL];   // u after LN1+part_t; later reused as yn (LN2 out)
__device__ float  g_yf[BB*HH*LL];   // fwd scan contrib; later y = gelu(yf+yb+u*D)
__device__ float  g_yb[BB*HH*LL];   // bwd scan contrib
__device__ float  g_z [BB*O2*LL];   // z (pre-GLU); later reused as h1 (FFN mid)
__device__ float  g_y1[BB*HH*LL];   // residual-1 output

// ---------------- helpers ---------------------------------------------------
__device__ __forceinline__ float gelu_t(float x) {
    float x3 = x * x * x;
    return 0.5f * x * (1.0f + tanhf(0.7978845608028654f * (x + 0.044715f * x3)));
}
__device__ __forceinline__ float sigm(float x) { return 1.0f / (1.0f + expf(-x)); }

__device__ __forceinline__ uint32_t tf32r(float x) {
    uint32_t r; asm("cvt.rna.tf32.f32 %0, %1;" : "=r"(r) : "f"(x)); return r;
}

__device__ __forceinline__ void mma8(float* c, const uint32_t* a, const uint32_t* b) {
    asm volatile(
        "mma.sync.aligned.m16n8k8.row.col.f32.tf32.tf32.f32 "
        "{%0,%1,%2,%3}, {%4,%5,%6,%7}, {%8,%9}, {%0,%1,%2,%3};"
        : "+f"(c[0]), "+f"(c[1]), "+f"(c[2]), "+f"(c[3])
        : "r"(a[0]), "r"(a[1]), "r"(a[2]), "r"(a[3]), "r"(b[0]), "r"(b[1]));
}

// ---------------- setup: lambda and 2*C' coefficients -----------------------
__global__ void k_setup(const float* __restrict__ log_dt,
                        const float* __restrict__ A_re, const float* __restrict__ A_im,
                        const float* __restrict__ C_re, const float* __restrict__ C_im) {
    int h = blockIdx.x, n = threadIdx.x;
    int i = h * NN + n;
    float dt  = expf(log_dt[h]);
    float ar  = A_re[i] * dt, ai = A_im[i] * dt;    // dtA
    float e   = expf(ar);
    float lre = e * cosf(ai), lim = e * sinf(ai);   // lambda = exp(dtA)
    float Are = A_re[i], Aim = A_im[i];
    float den = Are * Are + Aim * Aim;
    float num_r = lre - 1.0f, num_i = lim;
    float fre = (num_r * Are + num_i * Aim) / den;  // (lambda-1)/A
    float fim = (num_i * Are - num_r * Aim) / den;
    float c0r = C_re[i], c0i = C_im[i];
    float c1r = C_re[HH*NN + i], c1i = C_im[HH*NN + i];
    g_lam[i] = make_float2(lre, lim);
    g_c0[i]  = make_float2(2.0f*(c0r*fre - c0i*fim), 2.0f*(c0r*fim + c0i*fre));
    g_c1[i]  = make_float2(2.0f*(c1r*fre - c1i*fim), 2.0f*(c1r*fim + c1i*fre));
}

// ---------------- part_t = emb @ fc_t_w^T + b -------------------------------
__global__ void k_partt(const float* __restrict__ emb, const float* __restrict__ w,
                        const float* __restrict__ bias) {
    int gw   = blockIdx.x * 8 + (threadIdx.x >> 5);  // warp id: one per (b,h)
    int lane = threadIdx.x & 31;
    int b = gw >> 8, h = gw & 255;
    float s = 0.f;
    #pragma unroll
    for (int k = lane; k < DTE; k += 32)
        s += emb[b*DTE + k] * w[h*DTE + k];
    #pragma unroll
    for (int o = 16; o > 0; o >>= 1) s += __shfl_xor_sync(0xffffffffu, s, o);
    if (lane == 0) g_partt[b*HH + h] = s + bias[h];
}

// ---------------- per-(b,l) mean/rstd over H --------------------------------
__global__ void k_stats(const float* __restrict__ inp) {
    int b = blockIdx.y;
    int l = blockIdx.x * 256 + threadIdx.x;
    const float* p = inp + (size_t)b * HH * LL + l;
    float s = 0.f, sq = 0.f;
    #pragma unroll 8
    for (int h = 0; h < HH; h++) {
        float v = p[(size_t)h * LL];
        s += v; sq += v * v;
    }
    float mean = s * (1.0f / HH);
    float var  = sq * (1.0f / HH) - mean * mean;
    float rstd = rsqrtf(fmaxf(var, 1e-20f));
    g_stats[b*LL + l] = make_float2(mean, rstd);
}

// ---------------- LN1 + part_t -> u -----------------------------------------
__global__ void k_norm1(const float* __restrict__ x,
                        const float* __restrict__ n_m, const float* __restrict__ n_s) {
    float m0 = *n_m, s0 = *n_s;
    size_t i4 = (size_t)blockIdx.x * 256 + threadIdx.x;
    size_t idx = i4 * 4;
    int l = (int)(idx & (LL - 1));
    int h = (int)((idx >> 13) & (HH - 1));
    int b = (int)(idx >> 21);
    float pt = g_partt[b*HH + h];
    float4 xv = *(const float4*)(x + idx);
    float4 o;
    float2 st;
    st = g_stats[b*LL + l + 0]; o.x = s0*st.y*(xv.x - st.x + m0) + pt;
    st = g_stats[b*LL + l + 1]; o.y = s0*st.y*(xv.y - st.x + m0) + pt;
    st = g_stats[b*LL + l + 2]; o.z = s0*st.y*(xv.z - st.x + m0) + pt;
    st = g_stats[b*LL + l + 3]; o.w = s0*st.y*(xv.w - st.x + m0) + pt;
    *(float4*)(g_u + idx) = o;
}

// ---------------- bidirectional diagonal SSM scan ---------------------------
// warp = 2 heads x 16 modes/lane; gridDim.y selects direction.
__global__ void k_scan() {
    int warp = threadIdx.x >> 5, lane = threadIdx.x & 31;
    int pair = blockIdx.x * 4 + warp;          // 0..1023
    int sub  = lane >> 4, n = lane & 15;
    int bh   = pair * 2 + sub;                 // 0..2047
    int h    = bh & 255;
    int dir  = blockIdx.y;
    float2 lam = g_lam[h*NN + n];
    float2 c   = (dir == 0 ? g_c0 : g_c1)[h*NN + n];
    const float* u = g_u + (size_t)bh * LL;
    float* out = (dir == 0 ? g_yf : g_yb) + (size_t)bh * LL;
    float sr = 0.f, si = 0.f;
    if (dir == 0) {
        for (int l = 0; l < LL; l += 4) {
            float4 uv = *(const float4*)(u + l);
            float y0, y1, y2, y3, nr;
            nr = fmaf(lam.x, sr, fmaf(-lam.y, si, uv.x)); si = fmaf(lam.x, si, lam.y*sr); sr = nr;
            y0 = c.x*sr - c.y*si;
            nr = fmaf(lam.x, sr, fmaf(-lam.y, si, uv.y)); si = fmaf(lam.x, si, lam.y*sr); sr = nr;
            y1 = c.x*sr - c.y*si;
            nr = fmaf(lam.x, sr, fmaf(-lam.y, si, uv.z)); si = fmaf(lam.x, si, lam.y*sr); sr = nr;
            y2 = c.x*sr - c.y*si;
            nr = fmaf(lam.x, sr, fmaf(-lam.y, si, uv.w)); si = fmaf(lam.x, si, lam.y*sr); sr = nr;
            y3 = c.x*sr - c.y*si;
            #pragma unroll
            for (int o = 8; o > 0; o >>= 1) {
                y0 += __shfl_xor_sync(0xffffffffu, y0, o);
                y1 += __shfl_xor_sync(0xffffffffu, y1, o);
                y2 += __shfl_xor_sync(0xffffffffu, y2, o);
                y3 += __shfl_xor_sync(0xffffffffu, y3, o);
            }
            if (n == 0) *(float4*)(out + l) = make_float4(y0, y1, y2, y3);
        }
    } else {
        // t[l] = u[l+1] + lam*t[l+1]; y[l] = 2Re(c1' t[l])
        for (int l = LL - 1; l >= 3; l -= 4) {
            float4 uv = *(const float4*)(u + l - 3);   // u[l-3..l]
            float y0, y1, y2, y3, nr;
            y0 = c.x*sr - c.y*si;   // at l
            nr = fmaf(lam.x, sr, fmaf(-lam.y, si, uv.w)); si = fmaf(lam.x, si, lam.y*sr); sr = nr;
            y1 = c.x*sr - c.y*si;   // at l-1
            nr = fmaf(lam.x, sr, fmaf(-lam.y, si, uv.z)); si = fmaf(lam.x, si, lam.y*sr); sr = nr;
            y2 = c.x*sr - c.y*si;   // at l-2
            nr = fmaf(lam.x, sr, fmaf(-lam.y, si, uv.y)); si = fmaf(lam.x, si, lam.y*sr); sr = nr;
            y3 = c.x*sr - c.y*si;   // at l-3
            nr = fmaf(lam.x, sr, fmaf(-lam.y, si, uv.x)); si = fmaf(lam.x, si, lam.y*sr); sr = nr;
            #pragma unroll
            for (int o = 8; o > 0; o >>= 1) {
                y0 += __shfl_xor_sync(0xffffffffu, y0, o);
                y1 += __shfl_xor_sync(0xffffffffu, y1, o);
                y2 += __shfl_xor_sync(0xffffffffu, y2, o);
                y3 += __shfl_xor_sync(0xffffffffu, y3, o);
            }
            if (n == 0) *(float4*)(out + l - 3) = make_float4(y3, y2, y1, y0);
        }
    }
}

// ---------------- combine: y = gelu(yf + yb + u*D) -> g_yf ------------------
__global__ void k_combine(const float* __restrict__ D) {
    size_t i4 = (size_t)blockIdx.x * 256 + threadIdx.x;
    size_t idx = i4 * 4;
    int h = (int)((idx >> 13) & (HH - 1));
    float d = D[h];
    float4 a = *(const float4*)(g_yf + idx);
    float4 bv = *(const float4*)(g_yb + idx);
    float4 uv = *(const float4*)(g_u + idx);
    float4 o;
    o.x = gelu_t(a.x + bv.x + uv.x * d);
    o.y = gelu_t(a.y + bv.y + uv.y * d);
    o.z = gelu_t(a.z + bv.z + uv.z * d);
    o.w = gelu_t(a.w + bv.w + uv.w * d);
    *(float4*)(g_yf + idx) = o;
}

// ---------------- GLU + residual: y1 = x + z1*sigmoid(z2) -------------------
__global__ void k_glu(const float* __restrict__ x, const float* __restrict__ out_b) {
    size_t i4 = (size_t)blockIdx.x * 256 + threadIdx.x;
    size_t idx = i4 * 4;
    int l = (int)(idx & (LL - 1));
    int h = (int)((idx >> 13) & (HH - 1));
    int b = (int)(idx >> 21);
    float b1 = out_b[h], b2 = out_b[h + HH];
    const float* z1 = g_z + ((size_t)b * O2 + h) * LL + l;
    const float* z2 = g_z + ((size_t)b * O2 + h + HH) * LL + l;
    float4 a = *(const float4*)z1;
    float4 g = *(const float4*)z2;
    float4 xv = *(const float4*)(x + idx);
    float4 o;
    o.x = xv.x + (a.x + b1) * sigm(g.x + b2);
    o.y = xv.y + (a.y + b1) * sigm(g.y + b2);
    o.z = xv.z + (a.z + b1) * sigm(g.z + b2);
    o.w = xv.w + (a.w + b1) * sigm(g.w + b2);
    *(float4*)(g_y1 + idx) = o;
}

// ---------------- LN2 -> yn (into g_u) --------------------------------------
__global__ void k_norm2(const float* __restrict__ n_m, const float* __restrict__ n_s) {
    float m0 = *n_m, s0 = *n_s;
    size_t i4 = (size_t)blockIdx.x * 256 + threadIdx.x;
    size_t idx = i4 * 4;
    int l = (int)(idx & (LL - 1));
    int b = (int)(idx >> 21);
    float4 xv = *(const float4*)(g_y1 + idx);
    float4 o;
    float2 st;
    st = g_stats[b*LL + l + 0]; o.x = s0*st.y*(xv.x - st.x + m0);
    st = g_stats[b*LL + l + 1]; o.y = s0*st.y*(xv.y - st.x + m0);
    st = g_stats[b*LL + l + 2]; o.z = s0*st.y*(xv.z - st.x + m0);
    st = g_stats[b*LL + l + 3]; o.w = s0*st.y*(xv.w - st.x + m0);
    *(float4*)(g_u + idx) = o;
}

// ---------------- TF32 tensor-core GEMM -------------------------------------
// C[b,m,l] = sum_k A[m,k] * Bm[b,k,l]
// Block tile 128x128, BK=16, double-buffered smem, 8 warps (2x4), warp 64x32.
// mma.m16n8k8 tf32; inputs rounded to tf32 once at the smem store (cvt.rna).
// Smem swizzle: column ^ (8*(k&3)) -> all fragment LDS and all STS conflict-free.
// EPI 0: plain.  EPI 1: gelu(v+bias[m]).  EPI 2: v+bias[m]+res[b,m,l].
#define TBM 128
#define TBN 128
#define TBK 16

template <int EPI>
__global__ void __launch_bounds__(256, 2)
mma_gemm(const float* __restrict__ A, const float* __restrict__ Bm,
         float* __restrict__ C, const float* __restrict__ bias,
         const float* __restrict__ res, int M, int K) {
    __shared__ uint32_t As[2][TBK * TBM];
    __shared__ uint32_t Bs[2][TBK * TBN];

    int b = blockIdx.z;
    const float* Bp = Bm + (size_t)b * K * LL;
    float*       Cp = C  + (size_t)b * M * LL;
    const float* Rp = (EPI == 2) ? (res + (size_t)b * M * LL) : nullptr;

    int tid  = threadIdx.x;
    int lane = tid & 31;
    int warp = tid >> 5;
    int wm   = warp >> 2;      // 0..1 -> m offset wm*64
    int wn   = warp & 3;       // 0..3 -> n offset wn*32
    int gid  = lane >> 2;      // 0..7
    int tid4 = lane & 3;       // 0..3
    int swz  = 8 * tid4;       // fragment-read swizzle

    int m0 = blockIdx.y * TBM, n0 = blockIdx.x * TBN;

    float acc[4][4][4];
    #pragma unroll
    for (int i = 0; i < 4; i++)
        #pragma unroll
        for (int j = 0; j < 4; j++)
            #pragma unroll
            for (int r = 0; r < 4; r++) acc[i][j][r] = 0.f;

    // loader lambdas (manually inlined twice)
    float4 aR[2], bR[2];
    const int T = K >> 4;

    // ---- prefetch tile 0
    {
        int k0 = 0;
        #pragma unroll
        for (int it = 0; it < 2; it++) {
            int idx = it * 256 + tid;
            int m = idx & 127, kq = idx >> 7;                 // kq 0..3
            aR[it] = *(const float4*)(A + (size_t)(m0 + m) * K + k0 + kq * 4);
            int kb = idx >> 5, n4 = idx & 31;                 // kb 0..15
            bR[it] = *(const float4*)(Bp + (size_t)(k0 + kb) * LL + n0 + n4 * 4);
        }
    }
    // ---- store tile 0
    #pragma unroll
    for (int it = 0; it < 2; it++) {
        int idx = it * 256 + tid;
        int m = idx & 127, kq = idx >> 7;
        int k = kq * 4;
        As[0][(k + 0) * TBM + (m ^ 0 )] = tf32r(aR[it].x);
        As[0][(k + 1) * TBM + (m ^ 8 )] = tf32r(aR[it].y);
        As[0][(k + 2) * TBM + (m ^ 16)] = tf32r(aR[it].z);
        As[0][(k + 3) * TBM + (m ^ 24)] = tf32r(aR[it].w);
        int kb = idx >> 5, n4 = idx & 31;
        int n = (n4 * 4) ^ (8 * (kb & 3));
        uint32_t* dst = &Bs[0][kb * TBN + n];
        dst[0] = tf32r(bR[it].x); dst[1] = tf32r(bR[it].y);
        dst[2] = tf32r(bR[it].z); dst[3] = tf32r(bR[it].w);
    }
    __syncthreads();

    for (int t = 0; t < T; t++) {
        // prefetch next tile into regs
        if (t + 1 < T) {
            int k0 = (t + 1) << 4;
            #pragma unroll
            for (int it = 0; it < 2; it++) {
                int idx = it * 256 + tid;
                int m = idx & 127, kq = idx >> 7;
                aR[it] = *(const float4*)(A + (size_t)(m0 + m) * K + k0 + kq * 4);
                int kb = idx >> 5, n4 = idx & 31;
                bR[it] = *(const float4*)(Bp + (size_t)(k0 + kb) * LL + n0 + n4 * 4);
            }
        }
        // compute on current buffer
        {
            const uint32_t* Asb = As[t & 1];
            const uint32_t* Bsb = Bs[t & 1];
            #pragma unroll
            for (int kk = 0; kk < TBK; kk += 8) {
                uint32_t aF[4][4], bF[4][2];
                #pragma unroll
                for (int mt = 0; mt < 4; mt++) {
                    int r0 = wm * 64 + mt * 16 + gid;
                    int r1 = r0 + 8;
                    aF[mt][0] = Asb[(kk + tid4) * TBM + (r0 ^ swz)];
                    aF[mt][1] = Asb[(kk + tid4) * TBM + (r1 ^ swz)];
                    aF[mt][2] = Asb[(kk + tid4 + 4) * TBM + (r0 ^ swz)];
                    aF[mt][3] = Asb[(kk + tid4 + 4) * TBM + (r1 ^ swz)];
                }
                #pragma unroll
                for (int nt = 0; nt < 4; nt++) {
                    int cB = wn * 32 + nt * 8 + gid;
                    bF[nt][0] = Bsb[(kk + tid4) * TBN + (cB ^ swz)];
                    bF[nt][1] = Bsb[(kk + tid4 + 4) * TBN + (cB ^ swz)];
                }
                #pragma unroll
                for (int mt = 0; mt < 4; mt++)
                    #pragma unroll
                    for (int nt = 0; nt < 4; nt++)
                        mma8(acc[mt][nt], aF[mt], bF[nt]);
            }
        }
        // store next tile to the other buffer
        if (t + 1 < T) {
            uint32_t* Asn = As[(t + 1) & 1];
            uint32_t* Bsn = Bs[(t + 1) & 1];
            #pragma unroll
            for (int it = 0; it < 2; it++) {
                int idx = it * 256 + tid;
                int m = idx & 127, kq = idx >> 7;
                int k = kq * 4;
                Asn[(k + 0) * TBM + (m ^ 0 )] = tf32r(aR[it].x);
                Asn[(k + 1) * TBM + (m ^ 8 )] = tf32r(aR[it].y);
                Asn[(k + 2) * TBM + (m ^ 16)] = tf32r(aR[it].z);
                Asn[(k + 3) * TBM + (m ^ 24)] = tf32r(aR[it].w);
                int kb = idx >> 5, n4 = idx & 31;
                int n = (n4 * 4) ^ (8 * (kb & 3));
                uint32_t* dst = &Bsn[kb * TBN + n];
                dst[0] = tf32r(bR[it].x); dst[1] = tf32r(bR[it].y);
                dst[2] = tf32r(bR[it].z); dst[3] = tf32r(bR[it].w);
            }
        }
        __syncthreads();
    }

    // epilogue: c0=(r,c) c1=(r,c+1) c2=(r+8,c) c3=(r+8,c+1)
    #pragma unroll
    for (int mt = 0; mt < 4; mt++) {
        int rbase = m0 + wm * 64 + mt * 16 + gid;
        #pragma unroll
        for (int half = 0; half < 2; half++) {
            int m = rbase + half * 8;
            float bs = (EPI != 0) ? bias[m] : 0.f;
            size_t base = (size_t)m * LL + n0;
            #pragma unroll
            for (int nt = 0; nt < 4; nt++) {
                int col = wn * 32 + nt * 8 + tid4 * 2;
                float v0 = acc[mt][nt][half * 2 + 0];
                float v1 = acc[mt][nt][half * 2 + 1];
                if (EPI == 1) { v0 = gelu_t(v0 + bs); v1 = gelu_t(v1 + bs); }
                if (EPI == 2) { v0 += bs + Rp[base + col]; v1 += bs + Rp[base + col + 1]; }
                *(float2*)(Cp + base + col) = make_float2(v0, v1);
            }
        }
    }
}

// ---------------- launch ----------------------------------------------------
extern "C" void kernel_launch(void* const* d_in, const int* in_sizes, int n_in,
                              void* d_out, int out_size) {
    const float* x      = (const float*)d_in[0];
    const float* emb    = (const float*)d_in[1];
    const float* fc_t_w = (const float*)d_in[2];
    const float* fc_t_b = (const float*)d_in[3];
    const float* log_dt = (const float*)d_in[4];
    const float* A_re   = (const float*)d_in[5];
    const float* A_im   = (const float*)d_in[6];
    const float* C_re   = (const float*)d_in[7];
    const float* C_im   = (const float*)d_in[8];
    const float* Dp     = (const float*)d_in[9];
    const float* out_w  = (const float*)d_in[10];
    const float* out_b  = (const float*)d_in[11];
    const float* n1_m   = (const float*)d_in[12];
    const float* n1_s   = (const float*)d_in[13];
    const float* n2_m   = (const float*)d_in[14];
    const float* n2_s   = (const float*)d_in[15];
    const float* ff_w1  = (const float*)d_in[16];
    const float* ff_b1  = (const float*)d_in[17];
    const float* ff_w2  = (const float*)d_in[18];
    const float* ff_b2  = (const float*)d_in[19];
    float* out = (float*)d_out;

    float *p_yf, *p_z, *p_u, *p_y1;
    cudaGetSymbolAddress((void**)&p_yf, g_yf);
    cudaGetSymbolAddress((void**)&p_z,  g_z);
    cudaGetSymbolAddress((void**)&p_u,  g_u);
    cudaGetSymbolAddress((void**)&p_y1, g_y1);

    const int EW_BLOCKS = (BB * HH * LL) / (256 * 4);  // 16384

    k_setup<<<HH, NN>>>(log_dt, A_re, A_im, C_re, C_im);
    k_partt<<<(BB * HH) / 8, 256>>>(emb, fc_t_w, fc_t_b);
    k_stats<<<dim3(LL / 256, BB), 256>>>(x);
    k_norm1<<<EW_BLOCKS, 256>>>(x, n1_m, n1_s);
    k_scan<<<dim3((BB * HH) / 8, 2), 128>>>();
    k_combine<<<EW_BLOCKS, 256>>>(Dp);
    // z = out_w @ y
    mma_gemm<0><<<dim3(LL / TBN, O2 / TBM, BB), 256>>>(out_w, p_yf, p_z,
                                                       nullptr, nullptr, O2, HH);
    k_glu<<<EW_BLOCKS, 256>>>(x, out_b);
    k_stats<<<dim3(LL / 256, BB), 256>>>(p_y1);
    k_norm2<<<EW_BLOCKS, 256>>>(n2_m, n2_s);
    // h1 = gelu(ff_w1 @ yn + b1)  (yn in g_u, h1 overwrites g_z)
    mma_gemm<1><<<dim3(LL / TBN, DI / TBM, BB), 256>>>(ff_w1, p_u, p_z,
                                                       ff_b1, nullptr, DI, HH);
    // out = y1 + ff_w2 @ h1 + b2
    mma_gemm<2><<<dim3(LL / TBN, HH / TBM, BB), 256>>>(ff_w2, p_z, out,
                                                       ff_b2, p_y1, HH, DI);
}

// round 12
// speedup vs baseline: 1.5739x; 1.0391x over previous
#include <cuda_runtime.h>
#include <cuda_bf16.h>
#include <math.h>
#include <stdint.h>

#define BB 8
#define HH 256
#define LL 8192
#define NN 16
#define DTE 512
#define DI 512   // expand*H
#define O2 512   // 2*H

// ---------------- scratch (device globals; no allocation allowed) ----------
__device__ float  g_partt[BB*HH];
__device__ float2 g_stats[BB*LL];
__device__ float2 g_lam[HH*NN];
__device__ float2 g_c0[HH*NN];
__device__ float2 g_c1[HH*NN];
__device__ float  g_u [BB*HH*LL];   // u after LN1+part_t
__device__ float  g_yf[BB*HH*LL];   // fwd scan contrib; then y = gelu(yf+yb+u*D)
__device__ float  g_yb[BB*HH*LL];   // bwd scan contrib
__device__ float  g_z [BB*O2*LL];   // h1 (FFN mid)
__device__ float  g_y1[BB*HH*LL];   // residual-1 output

// ---------------- helpers ---------------------------------------------------
__device__ __forceinline__ float gelu_t(float x) {
    float x3 = x * x * x;
    return 0.5f * x * (1.0f + tanhf(0.7978845608028654f * (x + 0.044715f * x3)));
}
__device__ __forceinline__ float sigm(float x) { return 1.0f / (1.0f + expf(-x)); }

__device__ __forceinline__ uint32_t tf32r(float x) {
    uint32_t r; asm("cvt.rna.tf32.f32 %0, %1;" : "=r"(r) : "f"(x)); return r;
}

__device__ __forceinline__ void mma8(float* c, const uint32_t* a, const uint32_t* b) {
    asm volatile(
        "mma.sync.aligned.m16n8k8.row.col.f32.tf32.tf32.f32 "
        "{%0,%1,%2,%3}, {%4,%5,%6,%7}, {%8,%9}, {%0,%1,%2,%3};"
        : "+f"(c[0]), "+f"(c[1]), "+f"(c[2]), "+f"(c[3])
        : "r"(a[0]), "r"(a[1]), "r"(a[2]), "r"(a[3]), "r"(b[0]), "r"(b[1]));
}

// ---------------- setup: lambda and 2*C' coefficients -----------------------
__global__ void k_setup(const float* __restrict__ log_dt,
                        const float* __restrict__ A_re, const float* __restrict__ A_im,
                        const float* __restrict__ C_re, const float* __restrict__ C_im) {
    int h = blockIdx.x, n = threadIdx.x;
    int i = h * NN + n;
    float dt  = expf(log_dt[h]);
    float ar  = A_re[i] * dt, ai = A_im[i] * dt;    // dtA
    float e   = expf(ar);
    float lre = e * cosf(ai), lim = e * sinf(ai);   // lambda = exp(dtA)
    float Are = A_re[i], Aim = A_im[i];
    float den = Are * Are + Aim * Aim;
    float num_r = lre - 1.0f, num_i = lim;
    float fre = (num_r * Are + num_i * Aim) / den;  // (lambda-1)/A
    float fim = (num_i * Are - num_r * Aim) / den;
    float c0r = C_re[i], c0i = C_im[i];
    float c1r = C_re[HH*NN + i], c1i = C_im[HH*NN + i];
    g_lam[i] = make_float2(lre, lim);
    g_c0[i]  = make_float2(2.0f*(c0r*fre - c0i*fim), 2.0f*(c0r*fim + c0i*fre));
    g_c1[i]  = make_float2(2.0f*(c1r*fre - c1i*fim), 2.0f*(c1r*fim + c1i*fre));
}

// ---------------- part_t = emb @ fc_t_w^T + b -------------------------------
__global__ void k_partt(const float* __restrict__ emb, const float* __restrict__ w,
                        const float* __restrict__ bias) {
    int gw   = blockIdx.x * 8 + (threadIdx.x >> 5);  // warp id: one per (b,h)
    int lane = threadIdx.x & 31;
    int b = gw >> 8, h = gw & 255;
    float s = 0.f;
    #pragma unroll
    for (int k = lane; k < DTE; k += 32)
        s += emb[b*DTE + k] * w[h*DTE + k];
    #pragma unroll
    for (int o = 16; o > 0; o >>= 1) s += __shfl_xor_sync(0xffffffffu, s, o);
    if (lane == 0) g_partt[b*HH + h] = s + bias[h];
}

// ---------------- per-(b,l) mean/rstd over H (used before FFN) --------------
__global__ void k_stats(const float* __restrict__ inp) {
    int b = blockIdx.y;
    int l = blockIdx.x * 256 + threadIdx.x;
    const float* p = inp + (size_t)b * HH * LL + l;
    float s = 0.f, sq = 0.f;
    #pragma unroll 8
    for (int h = 0; h < HH; h++) {
        float v = p[(size_t)h * LL];
        s += v; sq += v * v;
    }
    float mean = s * (1.0f / HH);
    float var  = sq * (1.0f / HH) - mean * mean;
    float rstd = rsqrtf(fmaxf(var, 1e-20f));
    g_stats[b*LL + l] = make_float2(mean, rstd);
}

// ---------------- fused stats + LN1 + part_t -> u ---------------------------
// Block = (l-tile of 128) x (all 256 h) for one batch. Two passes over x;
// second pass hits L2 (148 concurrent tiles x 128KB = 19MB << L2).
__global__ void k_ln1(const float* __restrict__ x,
                      const float* __restrict__ n_m, const float* __restrict__ n_s) {
    __shared__ float ssum[8][132];
    __shared__ float ssq [8][132];
    __shared__ float2 sstat[128];
    int b = blockIdx.y;
    int l0 = blockIdx.x * 128;
    int warp = threadIdx.x >> 5, lane = threadIdx.x & 31;
    const float* xb = x + (size_t)b * HH * LL + l0;

    float s0=0.f,s1=0.f,s2=0.f,s3=0.f,q0=0.f,q1=0.f,q2=0.f,q3=0.f;
    for (int h = warp; h < HH; h += 8) {
        float4 v = *(const float4*)(xb + (size_t)h * LL + lane * 4);
        s0+=v.x; q0+=v.x*v.x; s1+=v.y; q1+=v.y*v.y;
        s2+=v.z; q2+=v.z*v.z; s3+=v.w; q3+=v.w*v.w;
    }
    ssum[warp][lane*4+0]=s0; ssum[warp][lane*4+1]=s1;
    ssum[warp][lane*4+2]=s2; ssum[warp][lane*4+3]=s3;
    ssq [warp][lane*4+0]=q0; ssq [warp][lane*4+1]=q1;
    ssq [warp][lane*4+2]=q2; ssq [warp][lane*4+3]=q3;
    __syncthreads();
    if (threadIdx.x < 128) {
        float S=0.f, Q=0.f;
        #pragma unroll
        for (int w = 0; w < 8; w++) { S += ssum[w][threadIdx.x]; Q += ssq[w][threadIdx.x]; }
        float mean = S * (1.0f/HH);
        float var  = Q * (1.0f/HH) - mean*mean;
        sstat[threadIdx.x] = make_float2(mean, rsqrtf(fmaxf(var, 1e-20f)));
    }
    __syncthreads();
    float m0 = *n_m, sc = *n_s;
    float* ub = g_u + (size_t)b * HH * LL + l0;
    float2 a0 = sstat[lane*4+0], a1 = sstat[lane*4+1];
    float2 a2 = sstat[lane*4+2], a3 = sstat[lane*4+3];
    for (int h = warp; h < HH; h += 8) {
        float4 v = *(const float4*)(xb + (size_t)h * LL + lane * 4);
        float pt = g_partt[b*HH + h];
        float4 o;
        o.x = sc*a0.y*(v.x - a0.x + m0) + pt;
        o.y = sc*a1.y*(v.y - a1.x + m0) + pt;
        o.z = sc*a2.y*(v.z - a2.x + m0) + pt;
        o.w = sc*a3.y*(v.w - a3.x + m0) + pt;
        *(float4*)(ub + (size_t)h * LL + lane * 4) = o;
    }
}

// ---------------- bidirectional diagonal SSM scan ---------------------------
// warp = 2 heads x 16 modes/lane; gridDim.y selects direction.
__global__ void k_scan() {
    int warp = threadIdx.x >> 5, lane = threadIdx.x & 31;
    int pair = blockIdx.x * 4 + warp;          // 0..1023
    int sub  = lane >> 4, n = lane & 15;
    int bh   = pair * 2 + sub;                 // 0..2047
    int h    = bh & 255;
    int dir  = blockIdx.y;
    float2 lam = g_lam[h*NN + n];
    float2 c   = (dir == 0 ? g_c0 : g_c1)[h*NN + n];
    const float* u = g_u + (size_t)bh * LL;
    float* out = (dir == 0 ? g_yf : g_yb) + (size_t)bh * LL;
    float sr = 0.f, si = 0.f;
    if (dir == 0) {
        for (int l = 0; l < LL; l += 4) {
            float4 uv = *(const float4*)(u + l);
            float y0, y1, y2, y3, nr;
            nr = fmaf(lam.x, sr, fmaf(-lam.y, si, uv.x)); si = fmaf(lam.x, si, lam.y*sr); sr = nr;
            y0 = c.x*sr - c.y*si;
            nr = fmaf(lam.x, sr, fmaf(-lam.y, si, uv.y)); si = fmaf(lam.x, si, lam.y*sr); sr = nr;
            y1 = c.x*sr - c.y*si;
            nr = fmaf(lam.x, sr, fmaf(-lam.y, si, uv.z)); si = fmaf(lam.x, si, lam.y*sr); sr = nr;
            y2 = c.x*sr - c.y*si;
            nr = fmaf(lam.x, sr, fmaf(-lam.y, si, uv.w)); si = fmaf(lam.x, si, lam.y*sr); sr = nr;
            y3 = c.x*sr - c.y*si;
            #pragma unroll
            for (int o = 8; o > 0; o >>= 1) {
                y0 += __shfl_xor_sync(0xffffffffu, y0, o);
                y1 += __shfl_xor_sync(0xffffffffu, y1, o);
                y2 += __shfl_xor_sync(0xffffffffu, y2, o);
                y3 += __shfl_xor_sync(0xffffffffu, y3, o);
            }
            if (n == 0) *(float4*)(out + l) = make_float4(y0, y1, y2, y3);
        }
    } else {
        for (int l = LL - 1; l >= 3; l -= 4) {
            float4 uv = *(const float4*)(u + l - 3);   // u[l-3..l]
            float y0, y1, y2, y3, nr;
            y0 = c.x*sr - c.y*si;   // at l
            nr = fmaf(lam.x, sr, fmaf(-lam.y, si, uv.w)); si = fmaf(lam.x, si, lam.y*sr); sr = nr;
            y1 = c.x*sr - c.y*si;   // at l-1
            nr = fmaf(lam.x, sr, fmaf(-lam.y, si, uv.z)); si = fmaf(lam.x, si, lam.y*sr); sr = nr;
            y2 = c.x*sr - c.y*si;   // at l-2
            nr = fmaf(lam.x, sr, fmaf(-lam.y, si, uv.y)); si = fmaf(lam.x, si, lam.y*sr); sr = nr;
            y3 = c.x*sr - c.y*si;   // at l-3
            nr = fmaf(lam.x, sr, fmaf(-lam.y, si, uv.x)); si = fmaf(lam.x, si, lam.y*sr); sr = nr;
            #pragma unroll
            for (int o = 8; o > 0; o >>= 1) {
                y0 += __shfl_xor_sync(0xffffffffu, y0, o);
                y1 += __shfl_xor_sync(0xffffffffu, y1, o);
                y2 += __shfl_xor_sync(0xffffffffu, y2, o);
                y3 += __shfl_xor_sync(0xffffffffu, y3, o);
            }
            if (n == 0) *(float4*)(out + l - 3) = make_float4(y3, y2, y1, y0);
        }
    }
}

// ---------------- combine: y = gelu(yf + yb + u*D) -> g_yf ------------------
__global__ void k_combine(const float* __restrict__ D) {
    size_t i4 = (size_t)blockIdx.x * 256 + threadIdx.x;
    size_t idx = i4 * 4;
    int h = (int)((idx >> 13) & (HH - 1));
    float d = D[h];
    float4 a = *(const float4*)(g_yf + idx);
    float4 bv = *(const float4*)(g_yb + idx);
    float4 uv = *(const float4*)(g_u + idx);
    float4 o;
    o.x = gelu_t(a.x + bv.x + uv.x * d);
    o.y = gelu_t(a.y + bv.y + uv.y * d);
    o.z = gelu_t(a.z + bv.z + uv.z * d);
    o.w = gelu_t(a.w + bv.w + uv.w * d);
    *(float4*)(g_yf + idx) = o;
}

#define TBK 16
#define TBN 128

// ---------------- fused out-linear + GLU + residual -------------------------
// Block computes W-rows [m0,m0+64) (value) and [m0+256,m0+320) (gate) against
// the same 128-wide B tile of y (in g_yf); epilogue writes
// y1 = x + (z1+b1)*sigmoid(z2+b2). z never hits memory.
__global__ void __launch_bounds__(256, 2)
gemm_glu(const float* __restrict__ W, const float* __restrict__ outb,
         const float* __restrict__ x) {
    __shared__ uint32_t As[2][2][TBK * 64];   // [buf][half]
    __shared__ uint32_t Bs[2][TBK * TBN];

    int b = blockIdx.z;
    const float* Bp = g_yf + (size_t)b * HH * LL;
    const float* xp = x    + (size_t)b * HH * LL;
    float*       Cp = g_y1 + (size_t)b * HH * LL;

    int tid  = threadIdx.x;
    int lane = tid & 31;
    int warp = tid >> 5;
    int wm   = warp >> 2;      // 0..1 -> m offset wm*32
    int wn   = warp & 3;       // 0..3 -> n offset wn*32
    int gid  = lane >> 2;      // 0..7
    int tid4 = lane & 3;       // 0..3
    int swz  = 8 * tid4;

    int m0 = blockIdx.y * 64, n0 = blockIdx.x * TBN;
    const int K = HH;
    const int T = K / TBK;     // 16

    float acc[2][2][4][4];
    #pragma unroll
    for (int hf = 0; hf < 2; hf++)
        #pragma unroll
        for (int i = 0; i < 2; i++)
            #pragma unroll
            for (int j = 0; j < 4; j++)
                #pragma unroll
                for (int r = 0; r < 4; r++) acc[hf][i][j][r] = 0.f;

    int a_row  = tid & 63;
    int a_colq = tid >> 6;     // 0..3 -> k cols a_colq*4..+3
    float4 aR[2], bR[2];

    // prefetch tile 0
    aR[0] = *(const float4*)(W + (size_t)(m0       + a_row) * K + a_colq * 4);
    aR[1] = *(const float4*)(W + (size_t)(m0 + 256 + a_row) * K + a_colq * 4);
    {
        int kb0 = tid >> 5, n4 = tid & 31;
        bR[0] = *(const float4*)(Bp + (size_t)kb0 * LL + n0 + n4 * 4);
        bR[1] = *(const float4*)(Bp + (size_t)(kb0 + 8) * LL + n0 + n4 * 4);
    }
    // store tile 0
    #pragma unroll
    for (int hf = 0; hf < 2; hf++) {
        int k = a_colq * 4;
        float4 v = aR[hf];
        As[0][hf][(k + 0) * 64 + (a_row ^ 0 )] = tf32r(v.x);
        As[0][hf][(k + 1) * 64 + (a_row ^ 8 )] = tf32r(v.y);
        As[0][hf][(k + 2) * 64 + (a_row ^ 16)] = tf32r(v.z);
        As[0][hf][(k + 3) * 64 + (a_row ^ 24)] = tf32r(v.w);
    }
    #pragma unroll
    for (int it = 0; it < 2; it++) {
        int kb = (tid >> 5) + it * 8, n4 = tid & 31;
        int nn_ = (n4 * 4) ^ (8 * (kb & 3));
        uint32_t* dst = &Bs[0][kb * TBN + nn_];
        float4 v = bR[it];
        dst[0] = tf32r(v.x); dst[1] = tf32r(v.y);
        dst[2] = tf32r(v.z); dst[3] = tf32r(v.w);
    }
    __syncthreads();

    for (int t = 0; t < T; t++) {
        if (t + 1 < T) {
            int k0 = (t + 1) << 4;
            aR[0] = *(const float4*)(W + (size_t)(m0       + a_row) * K + k0 + a_colq * 4);
            aR[1] = *(const float4*)(W + (size_t)(m0 + 256 + a_row) * K + k0 + a_colq * 4);
            int kb0 = tid >> 5, n4 = tid & 31;
            bR[0] = *(const float4*)(Bp + (size_t)(k0 + kb0) * LL + n0 + n4 * 4);
            bR[1] = *(const float4*)(Bp + (size_t)(k0 + kb0 + 8) * LL + n0 + n4 * 4);
        }
        {
            const uint32_t* A0 = As[t & 1][0];
            const uint32_t* A1 = As[t & 1][1];
            const uint32_t* Bsb = Bs[t & 1];
            #pragma unroll
            for (int kk = 0; kk < TBK; kk += 8) {
                uint32_t aF[2][2][4], bF[4][2];
                #pragma unroll
                for (int mt = 0; mt < 2; mt++) {
                    int r0 = wm * 32 + mt * 16 + gid;
                    int r1 = r0 + 8;
                    aF[0][mt][0] = A0[(kk + tid4) * 64 + (r0 ^ swz)];
                    aF[0][mt][1] = A0[(kk + tid4) * 64 + (r1 ^ swz)];
                    aF[0][mt][2] = A0[(kk + tid4 + 4) * 64 + (r0 ^ swz)];
                    aF[0][mt][3] = A0[(kk + tid4 + 4) * 64 + (r1 ^ swz)];
                    aF[1][mt][0] = A1[(kk + tid4) * 64 + (r0 ^ swz)];
                    aF[1][mt][1] = A1[(kk + tid4) * 64 + (r1 ^ swz)];
                    aF[1][mt][2] = A1[(kk + tid4 + 4) * 64 + (r0 ^ swz)];
                    aF[1][mt][3] = A1[(kk + tid4 + 4) * 64 + (r1 ^ swz)];
                }
                #pragma unroll
                for (int nt = 0; nt < 4; nt++) {
                    int cB = wn * 32 + nt * 8 + gid;
                    bF[nt][0] = Bsb[(kk + tid4) * TBN + (cB ^ swz)];
                    bF[nt][1] = Bsb[(kk + tid4 + 4) * TBN + (cB ^ swz)];
                }
                #pragma unroll
                for (int hf = 0; hf < 2; hf++)
                    #pragma unroll
                    for (int mt = 0; mt < 2; mt++)
                        #pragma unroll
                        for (int nt = 0; nt < 4; nt++)
                            mma8(acc[hf][mt][nt], aF[hf][mt], bF[nt]);
            }
        }
        if (t + 1 < T) {
            int bsel = (t + 1) & 1;
            #pragma unroll
            for (int hf = 0; hf < 2; hf++) {
                int k = a_colq * 4;
                float4 v = aR[hf];
                As[bsel][hf][(k + 0) * 64 + (a_row ^ 0 )] = tf32r(v.x);
                As[bsel][hf][(k + 1) * 64 + (a_row ^ 8 )] = tf32r(v.y);
                As[bsel][hf][(k + 2) * 64 + (a_row ^ 16)] = tf32r(v.z);
                As[bsel][hf][(k + 3) * 64 + (a_row ^ 24)] = tf32r(v.w);
            }
            #pragma unroll
            for (int it = 0; it < 2; it++) {
                int kb = (tid >> 5) + it * 8, n4 = tid & 31;
                int nn_ = (n4 * 4) ^ (8 * (kb & 3));
                uint32_t* dst = &Bs[bsel][kb * TBN + nn_];
                float4 v = bR[it];
                dst[0] = tf32r(v.x); dst[1] = tf32r(v.y);
                dst[2] = tf32r(v.z); dst[3] = tf32r(v.w);
            }
        }
        __syncthreads();
    }

    // epilogue: GLU + residual
    #pragma unroll
    for (int mt = 0; mt < 2; mt++) {
        #pragma unroll
        for (int hr = 0; hr < 2; hr++) {
            int h = m0 + wm * 32 + mt * 16 + gid + hr * 8;
            float b1 = outb[h], b2 = outb[h + 256];
            size_t base = (size_t)h * LL + n0;
            #pragma unroll
            for (int nt = 0; nt < 4; nt++) {
                int col = wn * 32 + nt * 8 + tid4 * 2;
                float v1a = acc[0][mt][nt][hr*2+0], v1b = acc[0][mt][nt][hr*2+1];
                float v2a = acc[1][mt][nt][hr*2+0], v2b = acc[1][mt][nt][hr*2+1];
                float xa = xp[base + col], xc = xp[base + col + 1];
                float o0 = xa + (v1a + b1) * sigm(v2a + b2);
                float o1 = xc + (v1b + b1) * sigm(v2b + b2);
                *(float2*)(Cp + base + col) = make_float2(o0, o1);
            }
        }
    }
}

// ---------------- TF32 tensor-core GEMM (FFN) -------------------------------
// C[b,m,l] = sum_k A[m,k] * Bm[b,k,l]
// PRO 1: B elements normalized on load (LN2 fused): s*rstd*(v-mean+m).
// EPI 1: gelu(v+bias[m]).  EPI 2: v+bias[m]+res[b,m,l].
#define TBM 128

template <int EPI, int PRO>
__global__ void __launch_bounds__(256, 2)
mma_gemm(const float* __restrict__ A, const float* __restrict__ Bm,
         float* __restrict__ C, const float* __restrict__ bias,
         const float* __restrict__ res,
         const float* __restrict__ nm, const float* __restrict__ ns,
         int M, int K) {
    __shared__ uint32_t As[2][TBK * TBM];
    __shared__ uint32_t Bs[2][TBK * TBN];

    int b = blockIdx.z;
    const float* Bp = Bm + (size_t)b * K * LL;
    float*       Cp = C  + (size_t)b * M * LL;
    const float* Rp = (EPI == 2) ? (res + (size_t)b * M * LL) : nullptr;

    int tid  = threadIdx.x;
    int lane = tid & 31;
    int warp = tid >> 5;
    int wm   = warp >> 2;
    int wn   = warp & 3;
    int gid  = lane >> 2;
    int tid4 = lane & 3;
    int swz  = 8 * tid4;

    int m0 = blockIdx.y * TBM, n0 = blockIdx.x * TBN;

    float2 stq[4]; float nmv = 0.f, nsv = 0.f;
    if (PRO) {
        nmv = *nm; nsv = *ns;
        #pragma unroll
        for (int j = 0; j < 4; j++)
            stq[j] = g_stats[(size_t)b * LL + n0 + (tid & 31) * 4 + j];
    }

    float acc[4][4][4];
    #pragma unroll
    for (int i = 0; i < 4; i++)
        #pragma unroll
        for (int j = 0; j < 4; j++)
            #pragma unroll
            for (int r = 0; r < 4; r++) acc[i][j][r] = 0.f;

    float4 aR[2], bR[2];
    const int T = K >> 4;

    {
        int k0 = 0;
        #pragma unroll
        for (int it = 0; it < 2; it++) {
            int idx = it * 256 + tid;
            int m = idx & 127, kq = idx >> 7;
            aR[it] = *(const float4*)(A + (size_t)(m0 + m) * K + k0 + kq * 4);
            int kb = idx >> 5, n4 = idx & 31;
            bR[it] = *(const float4*)(Bp + (size_t)(k0 + kb) * LL + n0 + n4 * 4);
        }
    }
    #pragma unroll
    for (int it = 0; it < 2; it++) {
        int idx = it * 256 + tid;
        int m = idx & 127, kq = idx >> 7;
        int k = kq * 4;
        As[0][(k + 0) * TBM + (m ^ 0 )] = tf32r(aR[it].x);
        As[0][(k + 1) * TBM + (m ^ 8 )] = tf32r(aR[it].y);
        As[0][(k + 2) * TBM + (m ^ 16)] = tf32r(aR[it].z);
        As[0][(k + 3) * TBM + (m ^ 24)] = tf32r(aR[it].w);
        int kb = idx >> 5, n4 = idx & 31;
        int n = (n4 * 4) ^ (8 * (kb & 3));
        uint32_t* dst = &Bs[0][kb * TBN + n];
        float4 v = bR[it];
        if (PRO) {
            v.x = nsv*stq[0].y*(v.x - stq[0].x + nmv);
            v.y = nsv*stq[1].y*(v.y - stq[1].x + nmv);
            v.z = nsv*stq[2].y*(v.z - stq[2].x + nmv);
            v.w = nsv*stq[3].y*(v.w - stq[3].x + nmv);
        }
        dst[0] = tf32r(v.x); dst[1] = tf32r(v.y);
        dst[2] = tf32r(v.z); dst[3] = tf32r(v.w);
    }
    __syncthreads();

    for (int t = 0; t < T; t++) {
        if (t + 1 < T) {
            int k0 = (t + 1) << 4;
            #pragma unroll
            for (int it = 0; it < 2; it++) {
                int idx = it * 256 + tid;
                int m = idx & 127, kq = idx >> 7;
                aR[it] = *(const float4*)(A + (size_t)(m0 + m) * K + k0 + kq * 4);
                int kb = idx >> 5, n4 = idx & 31;
                bR[it] = *(const float4*)(Bp + (size_t)(k0 + kb) * LL + n0 + n4 * 4);
            }
        }
        {
            const uint32_t* Asb = As[t & 1];
            const uint32_t* Bsb = Bs[t & 1];
            #pragma unroll
            for (int kk = 0; kk < TBK; kk += 8) {
                uint32_t aF[4][4], bF[4][2];
                #pragma unroll
                for (int mt = 0; mt < 4; mt++) {
                    int r0 = wm * 64 + mt * 16 + gid;
                    int r1 = r0 + 8;
                    aF[mt][0] = Asb[(kk + tid4) * TBM + (r0 ^ swz)];
                    aF[mt][1] = Asb[(kk + tid4) * TBM + (r1 ^ swz)];
                    aF[mt][2] = Asb[(kk + tid4 + 4) * TBM + (r0 ^ swz)];
                    aF[mt][3] = Asb[(kk + tid4 + 4) * TBM + (r1 ^ swz)];
                }
                #pragma unroll
                for (int nt = 0; nt < 4; nt++) {
                    int cB = wn * 32 + nt * 8 + gid;
                    bF[nt][0] = Bsb[(kk + tid4) * TBN + (cB ^ swz)];
                    bF[nt][1] = Bsb[(kk + tid4 + 4) * TBN + (cB ^ swz)];
                }
                #pragma unroll
                for (int mt = 0; mt < 4; mt++)
                    #pragma unroll
                    for (int nt = 0; nt < 4; nt++)
                        mma8(acc[mt][nt], aF[mt], bF[nt]);
            }
        }
        if (t + 1 < T) {
            uint32_t* Asn = As[(t + 1) & 1];
            uint32_t* Bsn = Bs[(t + 1) & 1];
            #pragma unroll
            for (int it = 0; it < 2; it++) {
                int idx = it * 256 + tid;
                int m = idx & 127, kq = idx >> 7;
                int k = kq * 4;
                Asn[(k + 0) * TBM + (m ^ 0 )] = tf32r(aR[it].x);
                Asn[(k + 1) * TBM + (m ^ 8 )] = tf32r(aR[it].y);
                Asn[(k + 2) * TBM + (m ^ 16)] = tf32r(aR[it].z);
                Asn[(k + 3) * TBM + (m ^ 24)] = tf32r(aR[it].w);
                int kb = idx >> 5, n4 = idx & 31;
                int n = (n4 * 4) ^ (8 * (kb & 3));
                uint32_t* dst = &Bsn[kb * TBN + n];
                float4 v = bR[it];
                if (PRO) {
                    v.x = nsv*stq[0].y*(v.x - stq[0].x + nmv);
                    v.y = nsv*stq[1].y*(v.y - stq[1].x + nmv);
                    v.z = nsv*stq[2].y*(v.z - stq[2].x + nmv);
                    v.w = nsv*stq[3].y*(v.w - stq[3].x + nmv);
                }
                dst[0] = tf32r(v.x); dst[1] = tf32r(v.y);
                dst[2] = tf32r(v.z); dst[3] = tf32r(v.w);
            }
        }
        __syncthreads();
    }

    #pragma unroll
    for (int mt = 0; mt < 4; mt++) {
        int rbase = m0 + wm * 64 + mt * 16 + gid;
        #pragma unroll
        for (int half = 0; half < 2; half++) {
            int m = rbase + half * 8;
            float bs = (EPI != 0) ? bias[m] : 0.f;
            size_t base = (size_t)m * LL + n0;
            #pragma unroll
            for (int nt = 0; nt < 4; nt++) {
                int col = wn * 32 + nt * 8 + tid4 * 2;
                float v0 = acc[mt][nt][half * 2 + 0];
                float v1 = acc[mt][nt][half * 2 + 1];
                if (EPI == 1) { v0 = gelu_t(v0 + bs); v1 = gelu_t(v1 + bs); }
                if (EPI == 2) { v0 += bs + Rp[base + col]; v1 += bs + Rp[base + col + 1]; }
                *(float2*)(Cp + base + col) = make_float2(v0, v1);
            }
        }
    }
}

// ---------------- launch ----------------------------------------------------
extern "C" void kernel_launch(void* const* d_in, const int* in_sizes, int n_in,
                              void* d_out, int out_size) {
    const float* x      = (const float*)d_in[0];
    const float* emb    = (const float*)d_in[1];
    const float* fc_t_w = (const float*)d_in[2];
    const float* fc_t_b = (const float*)d_in[3];
    const float* log_dt = (const float*)d_in[4];
    const float* A_re   = (const float*)d_in[5];
    const float* A_im   = (const float*)d_in[6];
    const float* C_re   = (const float*)d_in[7];
    const float* C_im   = (const float*)d_in[8];
    const float* Dp     = (const float*)d_in[9];
    const float* out_w  = (const float*)d_in[10];
    const float* out_b  = (const float*)d_in[11];
    const float* n1_m   = (const float*)d_in[12];
    const float* n1_s   = (const float*)d_in[13];
    const float* n2_m   = (const float*)d_in[14];
    const float* n2_s   = (const float*)d_in[15];
    const float* ff_w1  = (const float*)d_in[16];
    const float* ff_b1  = (const float*)d_in[17];
    const float* ff_w2  = (const float*)d_in[18];
    const float* ff_b2  = (const float*)d_in[19];
    float* out = (float*)d_out;

    float *p_z, *p_y1;
    cudaGetSymbolAddress((void**)&p_z,  g_z);
    cudaGetSymbolAddress((void**)&p_y1, g_y1);

    const int EW_BLOCKS = (BB * HH * LL) / (256 * 4);  // 16384

    k_setup<<<HH, NN>>>(log_dt, A_re, A_im, C_re, C_im);          // #0
    k_partt<<<(BB * HH) / 8, 256>>>(emb, fc_t_w, fc_t_b);         // #1
    k_ln1<<<dim3(LL / 128, BB), 256>>>(x, n1_m, n1_s);            // #2
    k_scan<<<dim3((BB * HH) / 8, 2), 128>>>();                    // #3
    k_combine<<<EW_BLOCKS, 256>>>(Dp);                            // #4
    // z = out_w @ y, GLU, +x  -> y1   (profiled launch #5)
    gemm_glu<<<dim3(LL / TBN, HH / 64, BB), 256>>>(out_w, out_b, x);
    k_stats<<<dim3(LL / 256, BB), 256>>>(p_y1);                   // #6
    // h1 = gelu(ff_w1 @ LN2(y1) + b1)
    mma_gemm<1, 1><<<dim3(LL / TBN, DI / TBM, BB), 256>>>(
        ff_w1, p_y1, p_z, ff_b1, nullptr, n2_m, n2_s, DI, HH);
    // out = y1 + ff_w2 @ h1 + b2
    mma_gemm<2, 0><<<dim3(LL / TBN, HH / TBM, BB), 256>>>(
        ff_w2, p_z, out, ff_b2, p_y1, nullptr, nullptr, HH, DI);
}